// round 2
// baseline (speedup 1.0000x reference)
#include <cuda_runtime.h>

#define B_ 16
#define T_ 8192
#define D_ 128
#define C_ 64
#define N_ 128

// Scratch (no allocation allowed): wo / per-chunk pre-state, and k_sum / pre-z.
__device__ float g_wo[(size_t)B_ * N_ * D_ * D_];   // 128 MB
__device__ float g_ks[(size_t)B_ * N_ * D_];        // 1 MB

__device__ __forceinline__ float lam_from(const float* __restrict__ ld) {
    return 1.0f / (1.0f + __expf(-ld[0]));
}

// ---------------------------------------------------------------------------
// Kernel A: per-chunk weighted outer product wo = (cd*K)^T V  and ksum.
// grid (N_, B_), 256 threads. smem: K tile (scaled), V tile, cd table.
// ---------------------------------------------------------------------------
__global__ __launch_bounds__(256) void wo_kernel(
    const float* __restrict__ k, const float* __restrict__ v,
    const float* __restrict__ ld)
{
    extern __shared__ float sm[];
    float* sk  = sm;                 // [64][128]  (pre-scaled by chunk_decay)
    float* sv  = sm + C_ * D_;       // [64][128]
    float* scd = sm + 2 * C_ * D_;   // [64]
    const int tid = threadIdx.x;
    const int n = blockIdx.x, b = blockIdx.y;

    const float lam = lam_from(ld);
    if (tid < C_) scd[tid] = powf(lam, (float)(C_ - 1 - tid));
    __syncthreads();

    const size_t base = ((size_t)b * T_ + (size_t)n * C_) * D_;
    for (int idx = tid; idx < C_ * D_; idx += 256) {
        int c = idx >> 7;
        sk[idx] = k[base + idx] * scd[c];
        sv[idx] = v[base + idx];
    }
    __syncthreads();

    const int ty = tid >> 4, tx = tid & 15;
    const int i0 = ty * 8, j0 = tx * 8;
    float acc[8][8];
#pragma unroll
    for (int u = 0; u < 8; u++)
#pragma unroll
        for (int w = 0; w < 8; w++) acc[u][w] = 0.f;

#pragma unroll 2
    for (int c = 0; c < C_; c++) {
        float4 a0 = *(const float4*)&sk[c * D_ + i0];
        float4 a1 = *(const float4*)&sk[c * D_ + i0 + 4];
        float4 b0 = *(const float4*)&sv[c * D_ + j0];
        float4 b1 = *(const float4*)&sv[c * D_ + j0 + 4];
        float av[8] = {a0.x, a0.y, a0.z, a0.w, a1.x, a1.y, a1.z, a1.w};
        float bv[8] = {b0.x, b0.y, b0.z, b0.w, b1.x, b1.y, b1.z, b1.w};
#pragma unroll
        for (int u = 0; u < 8; u++)
#pragma unroll
            for (int w = 0; w < 8; w++)
                acc[u][w] = fmaf(av[u], bv[w], acc[u][w]);
    }

    float* wbase = g_wo + (((size_t)b * N_ + n) << 14);
#pragma unroll
    for (int u = 0; u < 8; u++) {
        float4 s0 = make_float4(acc[u][0], acc[u][1], acc[u][2], acc[u][3]);
        float4 s1 = make_float4(acc[u][4], acc[u][5], acc[u][6], acc[u][7]);
        *(float4*)&wbase[(i0 + u) * D_ + j0]     = s0;
        *(float4*)&wbase[(i0 + u) * D_ + j0 + 4] = s1;
    }

    if (tid < D_) {
        float s = 0.f;
#pragma unroll 8
        for (int c = 0; c < C_; c++) s += sk[c * D_ + tid];
        g_ks[((size_t)b * N_ + n) * D_ + tid] = s;
    }
}

// ---------------------------------------------------------------------------
// Kernel B: in-place prefix scan over chunks. Each element of wo is replaced
// by the state BEFORE that chunk; final state goes to d_out state region.
// 262144 threads, 128 sequential steps each.
// ---------------------------------------------------------------------------
__global__ __launch_bounds__(256) void scan_state_kernel(
    const float* __restrict__ ld, float* __restrict__ out_state)
{
    const int gid = blockIdx.x * 256 + threadIdx.x;       // [0, B*D*D)
    const int b = gid >> 14;
    const int idx = gid & 16383;
    const float lam = lam_from(ld);
    const float r = powf(lam, (float)C_);
    float s = 0.f;
    float* p = g_wo + (((size_t)b * N_) << 14) + idx;
#pragma unroll 4
    for (int n = 0; n < N_; n++) {
        float w = p[(size_t)n << 14];
        p[(size_t)n << 14] = s;
        s = fmaf(r, s, w);
    }
    out_state[gid] = s;
}

__global__ __launch_bounds__(256) void scan_z_kernel(
    const float* __restrict__ ld, float* __restrict__ out_z)
{
    const int gid = blockIdx.x * 256 + threadIdx.x;       // [0, B*D)
    const int b = gid >> 7;
    const int d = gid & 127;
    const float lam = lam_from(ld);
    const float r = powf(lam, (float)C_);
    float s = 0.f;
    float* p = g_ks + (size_t)b * N_ * D_ + d;
#pragma unroll 4
    for (int n = 0; n < N_; n++) {
        float w = p[n * D_];
        p[n * D_] = s;
        s = fmaf(r, s, w);
    }
    out_z[gid] = s;
}

// ---------------------------------------------------------------------------
// Kernel C: per-chunk output.
//   attn  = (Q K^T) .* decay_mask        (64x64, k=128)
//   intra = attn V                        (64x128, k=64)
//   cross = Q state                       (64x128, k=128)
//   out   = (intra + decay_q[i]*cross) / max(max(rowsum,1)+decay_q[i]*(z.q),1)
// grid (N_, B_), 256 threads, ~189 KB smem.
// ---------------------------------------------------------------------------
__global__ __launch_bounds__(256) void out_kernel(
    const float* __restrict__ q, const float* __restrict__ k,
    const float* __restrict__ v, const float* __restrict__ ld,
    float* __restrict__ out)
{
    extern __shared__ float sm[];
    float* sqT  = sm;                  // [128][68]  Q transposed (d-major)
    float* skT  = sqT + 128 * 68;      // [128][68]  K transposed
    float* svv  = skT + 128 * 68;      // [64][132]  V row-major padded
    float* sst  = svv + 64 * 132;      // [128][132] state row-major padded
    float* sat  = sst + 128 * 132;     // [64][68]   attn i-major padded
    float* spw  = sat + 64 * 68;       // [68]       lam^t
    float* szv  = spw + 68;            // [128]      pre-chunk z
    float* sinv = szv + 128;           // [64]       1/total_z

    const int tid = threadIdx.x;
    const int n = blockIdx.x, b = blockIdx.y;
    const float lam = lam_from(ld);
    if (tid <= C_) spw[tid] = powf(lam, (float)tid);

    const size_t base = ((size_t)b * T_ + (size_t)n * C_) * D_;
    for (int idx = tid; idx < C_ * D_; idx += 256) {
        int c = idx >> 7, d = idx & 127;
        sqT[d * 68 + c] = q[base + idx];
        skT[d * 68 + c] = k[base + idx];
        svv[c * 132 + d] = v[base + idx];
    }
    {
        const float* st = g_wo + (((size_t)b * N_ + n) << 14);
        for (int idx = tid; idx < D_ * D_; idx += 256)
            sst[(idx >> 7) * 132 + (idx & 127)] = st[idx];
    }
    if (tid < D_) szv[tid] = g_ks[((size_t)b * N_ + n) * D_ + tid];
    __syncthreads();

    const int ty = tid >> 4, tx = tid & 15;
    const int i0 = ty * 4, j0 = tx * 4;

    // ---- GEMM1: S = Q K^T (64x64, k=128) ----
    float a1[4][4];
#pragma unroll
    for (int u = 0; u < 4; u++)
#pragma unroll
        for (int w = 0; w < 4; w++) a1[u][w] = 0.f;
#pragma unroll 4
    for (int d = 0; d < D_; d++) {
        float4 a  = *(const float4*)&sqT[d * 68 + i0];
        float4 bb = *(const float4*)&skT[d * 68 + j0];
        float av[4] = {a.x, a.y, a.z, a.w};
        float bv[4] = {bb.x, bb.y, bb.z, bb.w};
#pragma unroll
        for (int u = 0; u < 4; u++)
#pragma unroll
            for (int w = 0; w < 4; w++)
                a1[u][w] = fmaf(av[u], bv[w], a1[u][w]);
    }
    // mask + decay, write i-major
#pragma unroll
    for (int u = 0; u < 4; u++) {
        int i = i0 + u;
#pragma unroll
        for (int w = 0; w < 4; w++) {
            int j = j0 + w;
            float val = (j <= i) ? a1[u][w] * spw[i - j] : 0.f;
            sat[i * 68 + j] = val;
        }
    }
    __syncthreads();

    // ---- z normalization terms (threads 0..63, one row each) ----
    if (tid < C_) {
        const int i = tid;
        float rs = 0.f;
#pragma unroll 8
        for (int j = 0; j < C_; j++) rs += sat[i * 68 + j];
        float cz = 0.f;
#pragma unroll 8
        for (int d = 0; d < D_; d++) cz = fmaf(szv[d], sqT[d * 68 + i], cz);
        float dq = spw[i + 1];
        float iz = fmaxf(rs, 1.f);
        float tz = fmaxf(iz + dq * cz, 1.f);
        sinv[i] = 1.f / tz;
    }

    const int c0 = tx * 8;

    // ---- GEMM3: cross = Q state (64x128, k=128) ----
    float o2[4][8];
#pragma unroll
    for (int u = 0; u < 4; u++)
#pragma unroll
        for (int w = 0; w < 8; w++) o2[u][w] = 0.f;
#pragma unroll 2
    for (int d = 0; d < D_; d++) {
        float4 a  = *(const float4*)&sqT[d * 68 + i0];
        float av[4] = {a.x, a.y, a.z, a.w};
        float4 b0 = *(const float4*)&sst[d * 132 + c0];
        float4 b1 = *(const float4*)&sst[d * 132 + c0 + 4];
        float bv[8] = {b0.x, b0.y, b0.z, b0.w, b1.x, b1.y, b1.z, b1.w};
#pragma unroll
        for (int u = 0; u < 4; u++)
#pragma unroll
            for (int w = 0; w < 8; w++)
                o2[u][w] = fmaf(av[u], bv[w], o2[u][w]);
    }

    // ---- GEMM2: intra = attn V (64x128, k=64) ----
    float o1[4][8];
#pragma unroll
    for (int u = 0; u < 4; u++)
#pragma unroll
        for (int w = 0; w < 8; w++) o1[u][w] = 0.f;
#pragma unroll 2
    for (int j = 0; j < C_; j++) {
        float av[4];
#pragma unroll
        for (int u = 0; u < 4; u++) av[u] = sat[(i0 + u) * 68 + j];
        float4 b0 = *(const float4*)&svv[j * 132 + c0];
        float4 b1 = *(const float4*)&svv[j * 132 + c0 + 4];
        float bv[8] = {b0.x, b0.y, b0.z, b0.w, b1.x, b1.y, b1.z, b1.w};
#pragma unroll
        for (int u = 0; u < 4; u++)
#pragma unroll
            for (int w = 0; w < 8; w++)
                o1[u][w] = fmaf(av[u], bv[w], o1[u][w]);
    }
    __syncthreads();   // sinv visible to all

    // ---- combine + store ----
    float* ob = out + base;
#pragma unroll
    for (int u = 0; u < 4; u++) {
        int i = i0 + u;
        float dq  = spw[i + 1];
        float inv = sinv[i];
        float4 r0, r1;
        r0.x = fmaf(dq, o2[u][0], o1[u][0]) * inv;
        r0.y = fmaf(dq, o2[u][1], o1[u][1]) * inv;
        r0.z = fmaf(dq, o2[u][2], o1[u][2]) * inv;
        r0.w = fmaf(dq, o2[u][3], o1[u][3]) * inv;
        r1.x = fmaf(dq, o2[u][4], o1[u][4]) * inv;
        r1.y = fmaf(dq, o2[u][5], o1[u][5]) * inv;
        r1.z = fmaf(dq, o2[u][6], o1[u][6]) * inv;
        r1.w = fmaf(dq, o2[u][7], o1[u][7]) * inv;
        *(float4*)&ob[i * D_ + c0]     = r0;
        *(float4*)&ob[i * D_ + c0 + 4] = r1;
    }
}

// ---------------------------------------------------------------------------
extern "C" void kernel_launch(void* const* d_in, const int* in_sizes, int n_in,
                              void* d_out, int out_size)
{
    const float* q  = (const float*)d_in[0];
    const float* k  = (const float*)d_in[1];
    const float* v  = (const float*)d_in[2];
    const float* ld = (const float*)d_in[3];
    float* out = (float*)d_out;

    const int smemA = (2 * C_ * D_ + C_) * (int)sizeof(float);     // ~66 KB
    const int smemC = (128 * 68 * 2 + 64 * 132 + 128 * 132 + 64 * 68 + 68 + 128 + 64)
                      * (int)sizeof(float);                        // ~189 KB
    cudaFuncSetAttribute(wo_kernel,  cudaFuncAttributeMaxDynamicSharedMemorySize, smemA);
    cudaFuncSetAttribute(out_kernel, cudaFuncAttributeMaxDynamicSharedMemorySize, smemC);

    dim3 grid(N_, B_);
    float* out_state = out + (size_t)B_ * T_ * D_;                 // [B,D,D]
    float* out_z     = out_state + (size_t)B_ * D_ * D_;           // [B,D]

    wo_kernel<<<grid, 256, smemA>>>(k, v, ld);
    scan_state_kernel<<<(B_ * D_ * D_) / 256, 256>>>(ld, out_state);
    scan_z_kernel<<<(B_ * D_) / 256, 256>>>(ld, out_z);
    out_kernel<<<grid, 256, smemC>>>(q, k, v, ld, out);
}

// round 6
// speedup vs baseline: 1.2129x; 1.2129x over previous
#include <cuda_runtime.h>
#include <cstdint>

#define B_ 16
#define T_ 8192
#define D_ 128
#define C_ 64
#define N_ 128

// scratch: wo / pre-chunk state ([i][j] layout), ksum / pre-chunk z
__device__ float g_wo[(size_t)B_ * N_ * D_ * D_];
__device__ float g_ks[(size_t)B_ * N_ * D_];

__device__ __forceinline__ float lam_from(const float* __restrict__ ld) {
    return 1.0f / (1.0f + __expf(-ld[0]));
}
__device__ __forceinline__ float tf32r(float x) {
    uint32_t u; asm("cvt.rna.tf32.f32 %0, %1;" : "=r"(u) : "f"(x));
    return __uint_as_float(u);
}
__device__ __forceinline__ void split2(float x, uint32_t& h, uint32_t& l) {
    float hf = tf32r(x);
    h = __float_as_uint(hf);
    l = __float_as_uint(tf32r(x - hf));
}
// D(16x8) += A(16x8,row) * B(8x8, B[k][n])
__device__ __forceinline__ void mma8(float* d, const uint32_t* a, const uint32_t* b) {
    asm volatile(
        "mma.sync.aligned.m16n8k8.row.col.f32.tf32.tf32.f32 "
        "{%0,%1,%2,%3},{%4,%5,%6,%7},{%8,%9},{%0,%1,%2,%3};"
        : "+f"(d[0]), "+f"(d[1]), "+f"(d[2]), "+f"(d[3])
        : "r"(a[0]), "r"(a[1]), "r"(a[2]), "r"(a[3]), "r"(b[0]), "r"(b[1]));
}
// 3xTF32: d += a*b with a,b decomposed hi/lo
__device__ __forceinline__ void mma3(float* d, const uint32_t* ah, const uint32_t* al,
                                     const uint32_t* bh, const uint32_t* bl) {
    mma8(d, ah, bh);
    mma8(d, al, bh);
    mma8(d, ah, bl);
}

// ===========================================================================
// Kernel A: wo[i,j] = sum_c (cd_c k[c,i]) v[c,j].  3xTF32 (hi/lo in smem).
// grid (128,16), 256 threads (warp tiles 64x32).
// ===========================================================================
#define A_AH 0                     // 128*68
#define A_AL (A_AH + 8704)
#define A_BH (A_AL + 8704)         // 64*136
#define A_BL (A_BH + 8704)
#define A_RW (A_BL + 8704)         // 64*136 raw k stage
#define A_SC (A_RW + 8704)         // 64
#define A_FLOATS (A_SC + 64)

__global__ __launch_bounds__(256) void wo_kernel(
    const float* __restrict__ k, const float* __restrict__ v,
    const float* __restrict__ ld)
{
    extern __shared__ float sm[];
    float* AH = sm + A_AH; float* AL = sm + A_AL;
    float* BH = sm + A_BH; float* BL = sm + A_BL;
    float* RW = sm + A_RW; float* SC = sm + A_SC;
    const int tid = threadIdx.x;
    const int n = blockIdx.x, b = blockIdx.y;

    const float lam = lam_from(ld);
    if (tid < C_) SC[tid] = powf(lam, (float)(C_ - 1 - tid));
    const size_t gbase = ((size_t)b * T_ + (size_t)n * C_) * D_;

#pragma unroll
    for (int u = 0; u < 8; u++) {
        int e = tid + u * 256;
        int c = e >> 5, d0 = (e & 31) * 4;
        *(float4*)&RW[c * 136 + d0] = *(const float4*)&k[gbase + (size_t)c * D_ + d0];
    }
    __syncthreads();

    {
        const int i = tid >> 1, c0 = (tid & 1) * 32;
#pragma unroll
        for (int cc = 0; cc < 32; cc++) {
            int c = c0 + cc;
            float x = RW[c * 136 + i] * SC[c];
            float h = tf32r(x);
            AH[i * 68 + c] = h;
            AL[i * 68 + c] = tf32r(x - h);
        }
    }
#pragma unroll
    for (int u = 0; u < 8; u++) {
        int e = tid + u * 256;
        int c = e >> 5, d0 = (e & 31) * 4;
        float4 x = *(const float4*)&v[gbase + (size_t)c * D_ + d0];
        float h0 = tf32r(x.x), h1 = tf32r(x.y), h2 = tf32r(x.z), h3 = tf32r(x.w);
        *(float4*)&BH[c * 136 + d0] = make_float4(h0, h1, h2, h3);
        *(float4*)&BL[c * 136 + d0] =
            make_float4(tf32r(x.x - h0), tf32r(x.y - h1), tf32r(x.z - h2), tf32r(x.w - h3));
    }
    if (tid < D_) {
        float s = 0.f;
#pragma unroll 8
        for (int c = 0; c < C_; c++) s += RW[c * 136 + tid] * SC[c];
        g_ks[((size_t)b * N_ + n) * D_ + tid] = s;
    }
    __syncthreads();

    const int lane = tid & 31, g = lane >> 2, t4 = lane & 3, wid = tid >> 5;
    const int wm = wid >> 2, wn = wid & 3;
    float acc[4][4][4];
#pragma unroll
    for (int mi = 0; mi < 4; mi++)
#pragma unroll
        for (int ni = 0; ni < 4; ni++)
#pragma unroll
            for (int e = 0; e < 4; e++) acc[mi][ni][e] = 0.f;

#pragma unroll
    for (int pass = 0; pass < 3; pass++) {
        const float* Ab = (pass == 1) ? AL : AH;
        const float* Bb = (pass == 2) ? BL : BH;
#pragma unroll
        for (int ks = 0; ks < 8; ks++) {
            int kb = ks * 8;
            uint32_t a[4][4], bf[4][2];
#pragma unroll
            for (int mi = 0; mi < 4; mi++) {
                int r0 = wm * 64 + mi * 16 + g;
                a[mi][0] = __float_as_uint(Ab[r0 * 68 + kb + t4]);
                a[mi][1] = __float_as_uint(Ab[(r0 + 8) * 68 + kb + t4]);
                a[mi][2] = __float_as_uint(Ab[r0 * 68 + kb + t4 + 4]);
                a[mi][3] = __float_as_uint(Ab[(r0 + 8) * 68 + kb + t4 + 4]);
            }
#pragma unroll
            for (int ni = 0; ni < 4; ni++) {
                int n0 = wn * 32 + ni * 8 + g;
                bf[ni][0] = __float_as_uint(Bb[(kb + t4) * 136 + n0]);
                bf[ni][1] = __float_as_uint(Bb[(kb + t4 + 4) * 136 + n0]);
            }
#pragma unroll
            for (int mi = 0; mi < 4; mi++)
#pragma unroll
                for (int ni = 0; ni < 4; ni++)
                    mma8(acc[mi][ni], a[mi], bf[ni]);
        }
    }

    float* wb = g_wo + (((size_t)b * N_ + n) << 14);
#pragma unroll
    for (int mi = 0; mi < 4; mi++)
#pragma unroll
        for (int ni = 0; ni < 4; ni++) {
            int r0 = wm * 64 + mi * 16 + g, cc = wn * 32 + ni * 8 + 2 * t4;
            *(float2*)&wb[(size_t)r0 * D_ + cc]       = make_float2(acc[mi][ni][0], acc[mi][ni][1]);
            *(float2*)&wb[(size_t)(r0 + 8) * D_ + cc] = make_float2(acc[mi][ni][2], acc[mi][ni][3]);
        }
}

// ===========================================================================
// Kernel B: chunk scans (in-place; pre-chunk value left behind)
// ===========================================================================
__global__ __launch_bounds__(256) void scan_state_kernel(
    const float* __restrict__ ld, float* __restrict__ out_state)
{
    const int gid = blockIdx.x * 256 + threadIdx.x;
    const int b = gid >> 14;
    const int idx = gid & 16383;
    const float r = powf(lam_from(ld), (float)C_);
    float s = 0.f;
    float* p = g_wo + (((size_t)b * N_) << 14) + idx;
#pragma unroll 4
    for (int n = 0; n < N_; n++) {
        float w = p[(size_t)n << 14];
        p[(size_t)n << 14] = s;
        s = fmaf(r, s, w);
    }
    out_state[gid] = s;
}

__global__ __launch_bounds__(256) void scan_z_kernel(
    const float* __restrict__ ld, float* __restrict__ out_z)
{
    const int gid = blockIdx.x * 256 + threadIdx.x;
    const float r = powf(lam_from(ld), (float)C_);
    float s = 0.f;
    float* p = g_ks + ((size_t)(gid >> 7) * N_) * D_ + (gid & 127);
#pragma unroll 4
    for (int n = 0; n < N_; n++) {
        float w = p[n * D_];
        p[n * D_] = s;
        s = fmaf(r, s, w);
    }
    out_z[gid] = s;
}

// ===========================================================================
// Kernel C: per-chunk output via 3xTF32 mma.sync (in-register hi/lo split).
// All smem operands stay raw f32.
// grid (128,16), 256 threads.
// ===========================================================================
#define C_QR 0                      // 64*136  q rows (f32; later dq-scaled f32)
#define C_KT (C_QR + 8704)          // 128*72  kT (f32)
#define C_VR (C_KT + 9216)          // 64*136  v rows (f32)
#define C_ST (C_VR + 8704)          // 128*136 k-raw stage -> state (f32)
#define C_AT (C_ST + 17408)         // 64*72   attn (f32)
#define C_PW (C_AT + 4608)          // 68
#define C_RS (C_PW + 68)            // 64
#define C_IV (C_RS + 64)            // 64
#define C_SZ (C_IV + 64)            // 128
#define C_FLOATS (C_SZ + 128)

__global__ __launch_bounds__(256) void out_kernel(
    const float* __restrict__ q, const float* __restrict__ k,
    const float* __restrict__ v, const float* __restrict__ ld,
    float* __restrict__ out)
{
    extern __shared__ float sm[];
    float* QR = sm + C_QR; float* KT = sm + C_KT; float* VR = sm + C_VR;
    float* ST = sm + C_ST; float* AT = sm + C_AT;
    float* PW = sm + C_PW; float* RS = sm + C_RS; float* IV = sm + C_IV;
    float* SZ = sm + C_SZ;
    const int tid = threadIdx.x;
    const int n = blockIdx.x, b = blockIdx.y;
    const int lane = tid & 31, g = lane >> 2, t4 = lane & 3, wid = tid >> 5;

    const float lam = lam_from(ld);
    if (tid <= C_) PW[tid] = powf(lam, (float)tid);
    const size_t gbase = ((size_t)b * T_ + (size_t)n * C_) * D_;

    // phase 1: q raw -> QR, k raw -> ST, z -> SZ
#pragma unroll
    for (int u = 0; u < 8; u++) {
        int e = tid + u * 256;
        int c = e >> 5, d0 = (e & 31) * 4;
        *(float4*)&QR[c * 136 + d0] = *(const float4*)&q[gbase + (size_t)c * D_ + d0];
        *(float4*)&ST[c * 136 + d0] = *(const float4*)&k[gbase + (size_t)c * D_ + d0];
    }
    if (tid < D_) SZ[tid] = g_ks[((size_t)b * N_ + n) * D_ + tid];
    __syncthreads();

    // phase 2: transpose k -> KT (f32); v raw -> VR
    {
        const int i = tid >> 1, c0 = (tid & 1) * 32;
#pragma unroll
        for (int cc = 0; cc < 32; cc++) {
            int c = c0 + cc;
            KT[i * 72 + c] = ST[c * 136 + i];
        }
    }
#pragma unroll
    for (int u = 0; u < 8; u++) {
        int e = tid + u * 256;
        int c = e >> 5, d0 = (e & 31) * 4;
        *(float4*)&VR[c * 136 + d0] = *(const float4*)&v[gbase + (size_t)c * D_ + d0];
    }
    __syncthreads();

    // phase 3: warps 0-3 S = Q K^T (3xTF32) | warps 4-7 load state (raw f32)
    float sacc[8][4];
    if (wid < 4) {
#pragma unroll
        for (int ni = 0; ni < 8; ni++)
#pragma unroll
            for (int e = 0; e < 4; e++) sacc[ni][e] = 0.f;
#pragma unroll
        for (int ks = 0; ks < 16; ks++) {
            int kb = ks * 8;
            int r0 = wid * 16 + g;
            uint32_t ah[4], al[4];
            split2(QR[r0 * 136 + kb + t4],           ah[0], al[0]);
            split2(QR[(r0 + 8) * 136 + kb + t4],     ah[1], al[1]);
            split2(QR[r0 * 136 + kb + t4 + 4],       ah[2], al[2]);
            split2(QR[(r0 + 8) * 136 + kb + t4 + 4], ah[3], al[3]);
#pragma unroll
            for (int ni = 0; ni < 8; ni++) {
                int n0 = ni * 8 + g;
                uint32_t bh[2], bl[2];
                split2(KT[(kb + t4) * 72 + n0],     bh[0], bl[0]);
                split2(KT[(kb + t4 + 4) * 72 + n0], bh[1], bl[1]);
                mma3(sacc[ni], ah, al, bh, bl);
            }
        }
    } else {
        const float* gst = g_wo + (((size_t)b * N_ + n) << 14);
        const int t = tid - 128;
#pragma unroll
        for (int u = 0; u < 32; u++) {
            int e = t + u * 128;
            int r = e >> 5, d0 = (e & 31) * 4;
            *(float4*)&ST[r * 136 + d0] = *(const float4*)&gst[(size_t)r * D_ + d0];
        }
    }
    __syncthreads();

    // phase 4: warps 0-3 attn epilogue (mask/decay/rowsum, store f32) | warps 4-7 dq-scale Q (f32)
    if (wid < 4) {
        int r0 = wid * 16 + g, r1 = r0 + 8;
        float rs0 = 0.f, rs1 = 0.f;
#pragma unroll
        for (int ni = 0; ni < 8; ni++) {
            int cb = ni * 8 + 2 * t4;
            float v0 = (cb     <= r0) ? sacc[ni][0] * PW[r0 - cb]     : 0.f;
            float v1 = (cb + 1 <= r0) ? sacc[ni][1] * PW[r0 - cb - 1] : 0.f;
            float v2 = (cb     <= r1) ? sacc[ni][2] * PW[r1 - cb]     : 0.f;
            float v3 = (cb + 1 <= r1) ? sacc[ni][3] * PW[r1 - cb - 1] : 0.f;
            rs0 += v0 + v1; rs1 += v2 + v3;
            *(float2*)&AT[r0 * 72 + cb] = make_float2(v0, v1);
            *(float2*)&AT[r1 * 72 + cb] = make_float2(v2, v3);
        }
        rs0 += __shfl_xor_sync(0xffffffffu, rs0, 1);
        rs0 += __shfl_xor_sync(0xffffffffu, rs0, 2);
        rs1 += __shfl_xor_sync(0xffffffffu, rs1, 1);
        rs1 += __shfl_xor_sync(0xffffffffu, rs1, 2);
        if (t4 == 0) { RS[r0] = rs0; RS[r1] = rs1; }
    } else {
        const int t = tid - 128;
#pragma unroll
        for (int u = 0; u < 16; u++) {
            int e = t + u * 128;
            int r = e >> 5, d0 = (e & 31) * 4;
            float dq = PW[r + 1];
            float4* p = (float4*)&QR[r * 136 + d0];
            float4 x = *p;
            *p = make_float4(x.x * dq, x.y * dq, x.z * dq, x.w * dq);
        }
    }
    __syncthreads();

    // phase 5: inv[c] = 1/max(max(rowsum,1) + (dq q).z, 1)   (all f32 exact)
    if (tid < C_) {
        float cz = 0.f;
#pragma unroll 8
        for (int i = 0; i < D_; i++) cz = fmaf(QR[tid * 136 + i], SZ[i], cz);
        float iz = fmaxf(RS[tid], 1.f);
        IV[tid] = 1.f / fmaxf(iz + cz, 1.f);
    }
    __syncthreads();

    // phase 6: out = attn*V (k=64) + (dq Q)*state (k=128), both 3xTF32
    const int wm = wid & 3, wn = wid >> 2;
    float oacc[8][4];
#pragma unroll
    for (int ni = 0; ni < 8; ni++)
#pragma unroll
        for (int e = 0; e < 4; e++) oacc[ni][e] = 0.f;

#pragma unroll
    for (int ks = 0; ks < 8; ks++) {           // intra: A=attn, B=V
        int kb = ks * 8;
        int r0 = wm * 16 + g;
        uint32_t ah[4], al[4];
        split2(AT[r0 * 72 + kb + t4],           ah[0], al[0]);
        split2(AT[(r0 + 8) * 72 + kb + t4],     ah[1], al[1]);
        split2(AT[r0 * 72 + kb + t4 + 4],       ah[2], al[2]);
        split2(AT[(r0 + 8) * 72 + kb + t4 + 4], ah[3], al[3]);
#pragma unroll
        for (int ni = 0; ni < 8; ni++) {
            int n0 = wn * 64 + ni * 8 + g;
            uint32_t bh[2], bl[2];
            split2(VR[(kb + t4) * 136 + n0],     bh[0], bl[0]);
            split2(VR[(kb + t4 + 4) * 136 + n0], bh[1], bl[1]);
            mma3(oacc[ni], ah, al, bh, bl);
        }
    }
#pragma unroll
    for (int ks = 0; ks < 16; ks++) {          // cross: A=dq*Q, B=state
        int kb = ks * 8;
        int r0 = wm * 16 + g;
        uint32_t ah[4], al[4];
        split2(QR[r0 * 136 + kb + t4],           ah[0], al[0]);
        split2(QR[(r0 + 8) * 136 + kb + t4],     ah[1], al[1]);
        split2(QR[r0 * 136 + kb + t4 + 4],       ah[2], al[2]);
        split2(QR[(r0 + 8) * 136 + kb + t4 + 4], ah[3], al[3]);
#pragma unroll
        for (int ni = 0; ni < 8; ni++) {
            int n0 = wn * 64 + ni * 8 + g;
            uint32_t bh[2], bl[2];
            split2(ST[(kb + t4) * 136 + n0],     bh[0], bl[0]);
            split2(ST[(kb + t4 + 4) * 136 + n0], bh[1], bl[1]);
            mma3(oacc[ni], ah, al, bh, bl);
        }
    }

    // phase 7: normalize + store
    const float inv0 = IV[wm * 16 + g], inv1 = IV[wm * 16 + g + 8];
    float* ob = out + gbase;
#pragma unroll
    for (int ni = 0; ni < 8; ni++) {
        int cc = wn * 64 + ni * 8 + 2 * t4;
        int r0 = wm * 16 + g;
        *(float2*)&ob[(size_t)r0 * D_ + cc]       = make_float2(oacc[ni][0] * inv0, oacc[ni][1] * inv0);
        *(float2*)&ob[(size_t)(r0 + 8) * D_ + cc] = make_float2(oacc[ni][2] * inv1, oacc[ni][3] * inv1);
    }
}

// ---------------------------------------------------------------------------
extern "C" void kernel_launch(void* const* d_in, const int* in_sizes, int n_in,
                              void* d_out, int out_size)
{
    const float* q  = (const float*)d_in[0];
    const float* k  = (const float*)d_in[1];
    const float* v  = (const float*)d_in[2];
    const float* ld = (const float*)d_in[3];
    float* out = (float*)d_out;

    const int smemA = A_FLOATS * (int)sizeof(float);
    const int smemC = C_FLOATS * (int)sizeof(float);
    cudaFuncSetAttribute(wo_kernel,  cudaFuncAttributeMaxDynamicSharedMemorySize, smemA);
    cudaFuncSetAttribute(out_kernel, cudaFuncAttributeMaxDynamicSharedMemorySize, smemC);

    float* out_state = out + (size_t)B_ * T_ * D_;
    float* out_z     = out_state + (size_t)B_ * D_ * D_;

    wo_kernel<<<dim3(N_, B_), 256, smemA>>>(k, v, ld);
    scan_state_kernel<<<(B_ * D_ * D_) / 256, 256>>>(ld, out_state);
    scan_z_kernel<<<(B_ * D_) / 256, 256>>>(ld, out_z);
    out_kernel<<<dim3(N_, B_), 256, smemC>>>(q, k, v, ld, out);
}

// round 7
// speedup vs baseline: 1.5593x; 1.2856x over previous
#include <cuda_runtime.h>
#include <cstdint>

#define B_ 16
#define T_ 8192
#define D_ 128
#define C_ 64
#define N_ 128

// scratch: wo / pre-chunk state ([i][j] layout), ksum / pre-chunk z
__device__ float g_wo[(size_t)B_ * N_ * D_ * D_];
__device__ float g_ks[(size_t)B_ * N_ * D_];

__device__ __forceinline__ float lam_from(const float* __restrict__ ld) {
    return 1.0f / (1.0f + __expf(-ld[0]));
}
__device__ __forceinline__ float tf32r(float x) {
    uint32_t u; asm("cvt.rna.tf32.f32 %0, %1;" : "=r"(u) : "f"(x));
    return __uint_as_float(u);
}
__device__ __forceinline__ void split2(float x, uint32_t& h, uint32_t& l) {
    float hf = tf32r(x);
    h = __float_as_uint(hf);
    l = __float_as_uint(tf32r(x - hf));
}
// D(16x8) += A(16x8,row) * B(8x8, B[k][n])
__device__ __forceinline__ void mma8(float* d, const uint32_t* a, const uint32_t* b) {
    asm volatile(
        "mma.sync.aligned.m16n8k8.row.col.f32.tf32.tf32.f32 "
        "{%0,%1,%2,%3},{%4,%5,%6,%7},{%8,%9},{%0,%1,%2,%3};"
        : "+f"(d[0]), "+f"(d[1]), "+f"(d[2]), "+f"(d[3])
        : "r"(a[0]), "r"(a[1]), "r"(a[2]), "r"(a[3]), "r"(b[0]), "r"(b[1]));
}
// 3xTF32: d += a*b with a,b decomposed hi/lo
__device__ __forceinline__ void mma3(float* d, const uint32_t* ah, const uint32_t* al,
                                     const uint32_t* bh, const uint32_t* bl) {
    mma8(d, ah, bh);
    mma8(d, al, bh);
    mma8(d, ah, bl);
}

// ===========================================================================
// Kernel A: wo[i,j] = sum_c (cd_c k[c,i]) v[c,j].  3xTF32 (hi/lo in smem).
// grid (128,16), 512 threads (warp tiles 32x32, 16 warps).
// ===========================================================================
#define A_AH 0                     // 128*68
#define A_AL (A_AH + 8704)
#define A_BH (A_AL + 8704)         // 64*136
#define A_BL (A_BH + 8704)
#define A_RW (A_BL + 8704)         // 64*136 raw k stage
#define A_SC (A_RW + 8704)         // 64
#define A_FLOATS (A_SC + 64)

__global__ __launch_bounds__(512) void wo_kernel(
    const float* __restrict__ k, const float* __restrict__ v,
    const float* __restrict__ ld)
{
    extern __shared__ float sm[];
    float* AH = sm + A_AH; float* AL = sm + A_AL;
    float* BH = sm + A_BH; float* BL = sm + A_BL;
    float* RW = sm + A_RW; float* SC = sm + A_SC;
    const int tid = threadIdx.x;
    const int n = blockIdx.x, b = blockIdx.y;

    const float lam = lam_from(ld);
    if (tid < C_) SC[tid] = powf(lam, (float)(C_ - 1 - tid));
    const size_t gbase = ((size_t)b * T_ + (size_t)n * C_) * D_;

#pragma unroll
    for (int u = 0; u < 4; u++) {
        int e = tid + u * 512;
        int c = e >> 5, d0 = (e & 31) * 4;
        *(float4*)&RW[c * 136 + d0] = *(const float4*)&k[gbase + (size_t)c * D_ + d0];
    }
    __syncthreads();

    {   // transpose+scale k -> AH/AL: thread (i = tid>>2, c block = (tid&3)*16)
        const int i = tid >> 2, c0 = (tid & 3) * 16;
#pragma unroll
        for (int cc = 0; cc < 16; cc++) {
            int c = c0 + cc;
            float x = RW[c * 136 + i] * SC[c];
            float h = tf32r(x);
            AH[i * 68 + c] = h;
            AL[i * 68 + c] = tf32r(x - h);
        }
    }
#pragma unroll
    for (int u = 0; u < 4; u++) {
        int e = tid + u * 512;
        int c = e >> 5, d0 = (e & 31) * 4;
        float4 x = *(const float4*)&v[gbase + (size_t)c * D_ + d0];
        float h0 = tf32r(x.x), h1 = tf32r(x.y), h2 = tf32r(x.z), h3 = tf32r(x.w);
        *(float4*)&BH[c * 136 + d0] = make_float4(h0, h1, h2, h3);
        *(float4*)&BL[c * 136 + d0] =
            make_float4(tf32r(x.x - h0), tf32r(x.y - h1), tf32r(x.z - h2), tf32r(x.w - h3));
    }
    if (tid < D_) {
        float s = 0.f;
#pragma unroll 8
        for (int c = 0; c < C_; c++) s += RW[c * 136 + tid] * SC[c];
        g_ks[((size_t)b * N_ + n) * D_ + tid] = s;
    }
    __syncthreads();

    const int lane = tid & 31, g = lane >> 2, t4 = lane & 3, wid = tid >> 5;
    const int wm = wid >> 2, wn = wid & 3;      // 4x4 warp grid, tiles 32x32
    float acc[2][4][4];
#pragma unroll
    for (int mi = 0; mi < 2; mi++)
#pragma unroll
        for (int ni = 0; ni < 4; ni++)
#pragma unroll
            for (int e = 0; e < 4; e++) acc[mi][ni][e] = 0.f;

#pragma unroll
    for (int pass = 0; pass < 3; pass++) {
        const float* Ab = (pass == 1) ? AL : AH;
        const float* Bb = (pass == 2) ? BL : BH;
#pragma unroll
        for (int ks = 0; ks < 8; ks++) {
            int kb = ks * 8;
            uint32_t a[2][4], bf[4][2];
#pragma unroll
            for (int mi = 0; mi < 2; mi++) {
                int r0 = wm * 32 + mi * 16 + g;
                a[mi][0] = __float_as_uint(Ab[r0 * 68 + kb + t4]);
                a[mi][1] = __float_as_uint(Ab[(r0 + 8) * 68 + kb + t4]);
                a[mi][2] = __float_as_uint(Ab[r0 * 68 + kb + t4 + 4]);
                a[mi][3] = __float_as_uint(Ab[(r0 + 8) * 68 + kb + t4 + 4]);
            }
#pragma unroll
            for (int ni = 0; ni < 4; ni++) {
                int n0 = wn * 32 + ni * 8 + g;
                bf[ni][0] = __float_as_uint(Bb[(kb + t4) * 136 + n0]);
                bf[ni][1] = __float_as_uint(Bb[(kb + t4 + 4) * 136 + n0]);
            }
#pragma unroll
            for (int mi = 0; mi < 2; mi++)
#pragma unroll
                for (int ni = 0; ni < 4; ni++)
                    mma8(acc[mi][ni], a[mi], bf[ni]);
        }
    }

    float* wb = g_wo + (((size_t)b * N_ + n) << 14);
#pragma unroll
    for (int mi = 0; mi < 2; mi++)
#pragma unroll
        for (int ni = 0; ni < 4; ni++) {
            int r0 = wm * 32 + mi * 16 + g, cc = wn * 32 + ni * 8 + 2 * t4;
            *(float2*)&wb[(size_t)r0 * D_ + cc]       = make_float2(acc[mi][ni][0], acc[mi][ni][1]);
            *(float2*)&wb[(size_t)(r0 + 8) * D_ + cc] = make_float2(acc[mi][ni][2], acc[mi][ni][3]);
        }
}

// ===========================================================================
// Kernel B: chunk scans (in-place; pre-chunk value left behind).
// state scan vectorized float4: 65536 threads, 4 indep chains each.
// ===========================================================================
__global__ __launch_bounds__(256) void scan_state_kernel(
    const float* __restrict__ ld, float* __restrict__ out_state)
{
    const int gid = blockIdx.x * 256 + threadIdx.x;       // [0, B*D*D/4)
    const int b = gid >> 12;
    const int e4 = gid & 4095;
    const float r = powf(lam_from(ld), (float)C_);
    float4 s = make_float4(0.f, 0.f, 0.f, 0.f);
    float4* p = (float4*)(g_wo + (((size_t)b * N_) << 14)) + e4;
#pragma unroll 4
    for (int n = 0; n < N_; n++) {
        float4 w = p[(size_t)n << 12];
        p[(size_t)n << 12] = s;
        s.x = fmaf(r, s.x, w.x);
        s.y = fmaf(r, s.y, w.y);
        s.z = fmaf(r, s.z, w.z);
        s.w = fmaf(r, s.w, w.w);
    }
    ((float4*)out_state)[gid] = s;
}

__global__ __launch_bounds__(256) void scan_z_kernel(
    const float* __restrict__ ld, float* __restrict__ out_z)
{
    const int gid = blockIdx.x * 256 + threadIdx.x;
    const float r = powf(lam_from(ld), (float)C_);
    float s = 0.f;
    float* p = g_ks + ((size_t)(gid >> 7) * N_) * D_ + (gid & 127);
#pragma unroll 4
    for (int n = 0; n < N_; n++) {
        float w = p[n * D_];
        p[n * D_] = s;
        s = fmaf(r, s, w);
    }
    out_z[gid] = s;
}

// ===========================================================================
// Kernel C: per-chunk output via 3xTF32 mma.sync (in-register hi/lo split).
// grid (128,16), 512 threads (16 warps).
// ===========================================================================
#define C_QR 0                      // 64*136  q rows (f32; later dq-scaled f32)
#define C_KT (C_QR + 8704)          // 128*72  kT (f32)
#define C_VR (C_KT + 9216)          // 64*136  v rows (f32)
#define C_ST (C_VR + 8704)          // 128*136 k-raw stage -> state (f32)
#define C_AT (C_ST + 17408)         // 64*72   attn (f32)
#define C_PW (C_AT + 4608)          // 68
#define C_RS (C_PW + 68)            // 128 (2 partial halves)
#define C_IV (C_RS + 128)           // 64
#define C_SZ (C_IV + 64)            // 128
#define C_FLOATS (C_SZ + 128)

__global__ __launch_bounds__(512) void out_kernel(
    const float* __restrict__ q, const float* __restrict__ k,
    const float* __restrict__ v, const float* __restrict__ ld,
    float* __restrict__ out)
{
    extern __shared__ float sm[];
    float* QR = sm + C_QR; float* KT = sm + C_KT; float* VR = sm + C_VR;
    float* ST = sm + C_ST; float* AT = sm + C_AT;
    float* PW = sm + C_PW; float* RS = sm + C_RS; float* IV = sm + C_IV;
    float* SZ = sm + C_SZ;
    const int tid = threadIdx.x;
    const int n = blockIdx.x, b = blockIdx.y;
    const int lane = tid & 31, g = lane >> 2, t4 = lane & 3, wid = tid >> 5;

    const float lam = lam_from(ld);
    if (tid <= C_) PW[tid] = powf(lam, (float)tid);
    const size_t gbase = ((size_t)b * T_ + (size_t)n * C_) * D_;

    // phase 1: q raw -> QR, k raw -> ST, z -> SZ
#pragma unroll
    for (int u = 0; u < 4; u++) {
        int e = tid + u * 512;
        int c = e >> 5, d0 = (e & 31) * 4;
        *(float4*)&QR[c * 136 + d0] = *(const float4*)&q[gbase + (size_t)c * D_ + d0];
        *(float4*)&ST[c * 136 + d0] = *(const float4*)&k[gbase + (size_t)c * D_ + d0];
    }
    if (tid < D_) SZ[tid] = g_ks[((size_t)b * N_ + n) * D_ + tid];
    __syncthreads();

    // phase 2: transpose k -> KT (f32); v raw -> VR
    {
        const int i = tid >> 2, c0 = (tid & 3) * 16;
#pragma unroll
        for (int cc = 0; cc < 16; cc++) {
            int c = c0 + cc;
            KT[i * 72 + c] = ST[c * 136 + i];
        }
    }
#pragma unroll
    for (int u = 0; u < 4; u++) {
        int e = tid + u * 512;
        int c = e >> 5, d0 = (e & 31) * 4;
        *(float4*)&VR[c * 136 + d0] = *(const float4*)&v[gbase + (size_t)c * D_ + d0];
    }
    __syncthreads();

    // phase 3: warps 0-7: S = Q K^T (3xTF32), 16x32 tiles | warps 8-15: load state
    float sacc[4][4];
    const int swm = wid & 3, swn = wid >> 2;   // swn in {0,1} for wid<8
    if (wid < 8) {
#pragma unroll
        for (int ni = 0; ni < 4; ni++)
#pragma unroll
            for (int e = 0; e < 4; e++) sacc[ni][e] = 0.f;
#pragma unroll
        for (int ks = 0; ks < 16; ks++) {
            int kb = ks * 8;
            int r0 = swm * 16 + g;
            uint32_t ah[4], al[4];
            split2(QR[r0 * 136 + kb + t4],           ah[0], al[0]);
            split2(QR[(r0 + 8) * 136 + kb + t4],     ah[1], al[1]);
            split2(QR[r0 * 136 + kb + t4 + 4],       ah[2], al[2]);
            split2(QR[(r0 + 8) * 136 + kb + t4 + 4], ah[3], al[3]);
#pragma unroll
            for (int ni = 0; ni < 4; ni++) {
                int n0 = swn * 32 + ni * 8 + g;
                uint32_t bh[2], bl[2];
                split2(KT[(kb + t4) * 72 + n0],     bh[0], bl[0]);
                split2(KT[(kb + t4 + 4) * 72 + n0], bh[1], bl[1]);
                mma3(sacc[ni], ah, al, bh, bl);
            }
        }
    } else {
        const float* gst = g_wo + (((size_t)b * N_ + n) << 14);
        const int t = tid - 256;
#pragma unroll
        for (int u = 0; u < 16; u++) {
            int e = t + u * 256;
            int r = e >> 5, d0 = (e & 31) * 4;
            *(float4*)&ST[r * 136 + d0] = *(const float4*)&gst[(size_t)r * D_ + d0];
        }
    }
    __syncthreads();

    // phase 4: warps 0-7 attn epilogue (mask/decay/partial rowsum) | warps 8-15 dq-scale Q
    if (wid < 8) {
        int r0 = swm * 16 + g, r1 = r0 + 8;
        float rs0 = 0.f, rs1 = 0.f;
#pragma unroll
        for (int ni = 0; ni < 4; ni++) {
            int cb = swn * 32 + ni * 8 + 2 * t4;
            float v0 = (cb     <= r0) ? sacc[ni][0] * PW[r0 - cb]     : 0.f;
            float v1 = (cb + 1 <= r0) ? sacc[ni][1] * PW[r0 - cb - 1] : 0.f;
            float v2 = (cb     <= r1) ? sacc[ni][2] * PW[r1 - cb]     : 0.f;
            float v3 = (cb + 1 <= r1) ? sacc[ni][3] * PW[r1 - cb - 1] : 0.f;
            rs0 += v0 + v1; rs1 += v2 + v3;
            *(float2*)&AT[r0 * 72 + cb] = make_float2(v0, v1);
            *(float2*)&AT[r1 * 72 + cb] = make_float2(v2, v3);
        }
        rs0 += __shfl_xor_sync(0xffffffffu, rs0, 1);
        rs0 += __shfl_xor_sync(0xffffffffu, rs0, 2);
        rs1 += __shfl_xor_sync(0xffffffffu, rs1, 1);
        rs1 += __shfl_xor_sync(0xffffffffu, rs1, 2);
        if (t4 == 0) { RS[swn * 64 + r0] = rs0; RS[swn * 64 + r1] = rs1; }
    } else {
        const int t = tid - 256;
#pragma unroll
        for (int u = 0; u < 8; u++) {
            int e = t + u * 256;
            int r = e >> 5, d0 = (e & 31) * 4;
            float dq = PW[r + 1];
            float4* p = (float4*)&QR[r * 136 + d0];
            float4 x = *p;
            *p = make_float4(x.x * dq, x.y * dq, x.z * dq, x.w * dq);
        }
    }
    __syncthreads();

    // phase 5: inv[c] = 1/max(max(rowsum,1) + (dq q).z, 1)
    if (tid < C_) {
        float cz = 0.f;
#pragma unroll 8
        for (int i = 0; i < D_; i++) cz = fmaf(QR[tid * 136 + i], SZ[i], cz);
        float iz = fmaxf(RS[tid] + RS[64 + tid], 1.f);
        IV[tid] = 1.f / fmaxf(iz + cz, 1.f);
    }
    __syncthreads();

    // phase 6: out = attn*V (k=64) + (dq Q)*state (k=128), 3xTF32, 16x32 tiles
    const int wm = wid & 3, wn = wid >> 2;     // 4 x 4 warp grid
    float oacc[4][4];
#pragma unroll
    for (int ni = 0; ni < 4; ni++)
#pragma unroll
        for (int e = 0; e < 4; e++) oacc[ni][e] = 0.f;

#pragma unroll
    for (int ks = 0; ks < 8; ks++) {           // intra: A=attn, B=V
        int kb = ks * 8;
        int r0 = wm * 16 + g;
        uint32_t ah[4], al[4];
        split2(AT[r0 * 72 + kb + t4],           ah[0], al[0]);
        split2(AT[(r0 + 8) * 72 + kb + t4],     ah[1], al[1]);
        split2(AT[r0 * 72 + kb + t4 + 4],       ah[2], al[2]);
        split2(AT[(r0 + 8) * 72 + kb + t4 + 4], ah[3], al[3]);
#pragma unroll
        for (int ni = 0; ni < 4; ni++) {
            int n0 = wn * 32 + ni * 8 + g;
            uint32_t bh[2], bl[2];
            split2(VR[(kb + t4) * 136 + n0],     bh[0], bl[0]);
            split2(VR[(kb + t4 + 4) * 136 + n0], bh[1], bl[1]);
            mma3(oacc[ni], ah, al, bh, bl);
        }
    }
#pragma unroll
    for (int ks = 0; ks < 16; ks++) {          // cross: A=dq*Q, B=state
        int kb = ks * 8;
        int r0 = wm * 16 + g;
        uint32_t ah[4], al[4];
        split2(QR[r0 * 136 + kb + t4],           ah[0], al[0]);
        split2(QR[(r0 + 8) * 136 + kb + t4],     ah[1], al[1]);
        split2(QR[r0 * 136 + kb + t4 + 4],       ah[2], al[2]);
        split2(QR[(r0 + 8) * 136 + kb + t4 + 4], ah[3], al[3]);
#pragma unroll
        for (int ni = 0; ni < 4; ni++) {
            int n0 = wn * 32 + ni * 8 + g;
            uint32_t bh[2], bl[2];
            split2(ST[(kb + t4) * 136 + n0],     bh[0], bl[0]);
            split2(ST[(kb + t4 + 4) * 136 + n0], bh[1], bl[1]);
            mma3(oacc[ni], ah, al, bh, bl);
        }
    }

    // phase 7: normalize + store
    const float inv0 = IV[wm * 16 + g], inv1 = IV[wm * 16 + g + 8];
    float* ob = out + gbase;
#pragma unroll
    for (int ni = 0; ni < 4; ni++) {
        int cc = wn * 32 + ni * 8 + 2 * t4;
        int r0 = wm * 16 + g;
        *(float2*)&ob[(size_t)r0 * D_ + cc]       = make_float2(oacc[ni][0] * inv0, oacc[ni][1] * inv0);
        *(float2*)&ob[(size_t)(r0 + 8) * D_ + cc] = make_float2(oacc[ni][2] * inv1, oacc[ni][3] * inv1);
    }
}

// ---------------------------------------------------------------------------
extern "C" void kernel_launch(void* const* d_in, const int* in_sizes, int n_in,
                              void* d_out, int out_size)
{
    const float* q  = (const float*)d_in[0];
    const float* k  = (const float*)d_in[1];
    const float* v  = (const float*)d_in[2];
    const float* ld = (const float*)d_in[3];
    float* out = (float*)d_out;

    const int smemA = A_FLOATS * (int)sizeof(float);
    const int smemC = C_FLOATS * (int)sizeof(float);
    cudaFuncSetAttribute(wo_kernel,  cudaFuncAttributeMaxDynamicSharedMemorySize, smemA);
    cudaFuncSetAttribute(out_kernel, cudaFuncAttributeMaxDynamicSharedMemorySize, smemC);

    float* out_state = out + (size_t)B_ * T_ * D_;
    float* out_z     = out_state + (size_t)B_ * D_ * D_;

    wo_kernel<<<dim3(N_, B_), 512, smemA>>>(k, v, ld);
    scan_state_kernel<<<(B_ * D_ * D_ / 4) / 256, 256>>>(ld, out_state);
    scan_z_kernel<<<(B_ * D_) / 256, 256>>>(ld, out_z);
    out_kernel<<<dim3(N_, B_), 512, smemC>>>(q, k, v, ld, out);
}